// round 11
// baseline (speedup 1.0000x reference)
#include <cuda_runtime.h>
#include <math.h>

#define B_  32
#define T_  1024
#define D_  256
#define U_  512
#define G3  1536          // 3*U
#define NCTA_SCAN 128
#define CLUSTER 16        // CTAs per cluster == per batch-group
#define NGRP 8            // 8 groups x 4 batches
#define GB   4            // batches per group
#define WS_BYTES (96 * U_ * 4)   // 96 gate-cols x 512 k = 196608 B dynamic SMEM

typedef unsigned long long ull;

// packed fp32x2 FMA: d = a*b + d (elementwise on the two fp32 halves)
#define FMA2(d_, a_, b_) \
    asm("fma.rn.f32x2 %0, %1, %2, %3;" : "=l"(d_) : "l"(a_), "l"(b_), "l"(d_))
// splat a scalar float into both halves of a 64-bit packed reg
#define SPLAT2(d_, s_) \
    asm("mov.b64 %0, {%1, %1};" : "=l"(d_) : "r"(__float_as_uint(s_)))

// cluster barrier: arrive is RELEASE, wait is ACQUIRE at cluster scope (PTX
// defaults) — orders the __stcg h-stores against peer CTAs' next-step loads.
#define CLUSTER_SYNC() do { \
    asm volatile("barrier.cluster.arrive.aligned;" ::: "memory"); \
    asm volatile("barrier.cluster.wait.aligned;"   ::: "memory"); \
} while (0)

// fast sigmoid / tanh via MUFU.EX2 + MUFU.RCP (~1-2e-7 rel err)
__device__ __forceinline__ float fsig(float x) {
    float e, r;
    asm("ex2.approx.f32 %0, %1;" : "=f"(e) : "f"(x * -1.442695041f));
    asm("rcp.approx.f32 %0, %1;" : "=f"(r) : "f"(1.0f + e));
    return r;
}
__device__ __forceinline__ float ftanh(float x) {
    float e, r;
    asm("ex2.approx.f32 %0, %1;" : "=f"(e) : "f"(x * -2.885390082f));
    asm("rcp.approx.f32 %0, %1;" : "=f"(r) : "f"(1.0f + e));
    return fmaf(2.0f, r, -1.0f);
}

// ---------------- scratch (device globals: allocation-free contract) ----------
__device__ float g_xw[(size_t)T_ * B_ * G3];     // [T,B,3U] gate pre-activations
__device__ float g_out0[(size_t)T_ * B_ * U_];   // layer-0 outputs [T,B,U]
__device__ float g_pred0[(size_t)T_ * B_ * U_];  // layer-1 outputs
__device__ float g_pred1[(size_t)T_ * B_ * U_];  // layer-2 outputs
__device__ float g_h[2][B_ * U_];                // double-buffered hidden state

// ---------------- persistent GRU scan: 8 clusters of 16 CTAs ------------------
// Cluster/group g owns batches 4g..4g+3. CTA-in-cluster owns 32 units
// (96 gate cols in 196KB dynamic SMEM). Warp w -> units u0c+4w..+3, all 4
// batches. Lane l -> k in {4l+128*i2}. Step sync = HW cluster barrier.
__global__ void __launch_bounds__(256, 1) scan_kernel(
    const float* __restrict__ R,
    const float* __restrict__ brec,
    const float* __restrict__ h0vec,
    const float* __restrict__ xw,
    float* __restrict__ out,
    float* __restrict__ hbuf0,
    float* __restrict__ hbuf1)
{
    extern __shared__ float ws[];    // [c][k]: 96 x 512 floats

    const int tid = threadIdx.x;
    const int grp = blockIdx.x >> 4;          // 0..7 (== cluster id)
    const int cic = blockIdx.x & 15;          // CTA within cluster
    const int u0c = cic * 32;                 // first global unit owned

    // Preload 96 recurrent columns, coalesced over R:
    // idx -> (k, gate g, unit-offset uo): warp reads 32 consecutive R floats.
    for (int idx = tid; idx < 3 * 32 * U_; idx += 256) {
        int uo = idx & 31;
        int g  = (idx >> 5) % 3;
        int k  = idx / 96;
        int c  = (uo >> 2) * 12 + g * 4 + (uo & 3);   // warp-major col layout
        ws[c * U_ + k] = R[(size_t)k * G3 + g * U_ + u0c + uo];
    }

    // h init: CTA writes its (4 batches x 32 units) slice of hbuf0.
    if (tid < 128) {
        int bl = tid >> 5, ul = tid & 31;
        int u = u0c + ul;
        hbuf0[(grp * GB + bl) * U_ + u] = h0vec[u];
    }

    const int w  = tid >> 5, l = tid & 31;
    const float* wsq = ws + w * 12 * U_;      // this warp's 12 cols
    const int lb = l >> 2, uj = l & 3;
    const int gb = grp * GB + lb;             // batch handled by act-lane
    const int gu = u0c + w * 4 + uj;          // global unit handled
    const bool act = (l < 16);
    const unsigned bit0 = l & 1, bit1 = (l >> 1) & 1;
    const unsigned bit2 = (l >> 2) & 1, bit3 = (l >> 3) & 1;

    float bz = 0.f, brr = 0.f, bh = 0.f;
    if (act) {
        bz  = brec[gu];
        brr = brec[U_ + gu];
        bh  = brec[2 * U_ + gu];
    }

    float xz = 0.f, xr = 0.f, xh = 0.f;
    if (act) {
        const float* xwt = xw + (size_t)gb * G3;
        xz = __ldg(xwt + gu);
        xr = __ldg(xwt + U_ + gu);
        xh = __ldg(xwt + 2 * U_ + gu);
    }

    CLUSTER_SYNC();   // ws + h-init slices visible cluster-wide

    const int hb0 = grp * GB;                 // first batch row in h buffers

    for (int t = 0; t < T_; t++) {
        const float* hR = (t & 1) ? hbuf1 : hbuf0;
        float*       hW = (t & 1) ? hbuf0 : hbuf1;

        float hold = act ? __ldcg(hR + gb * U_ + gu) : 0.f;

        ull acc[4][12];
        #pragma unroll
        for (int b = 0; b < 4; b++)
            #pragma unroll
            for (int c = 0; c < 12; c++) acc[b][c] = 0ull;

        // staged h prefetch: load block i2+1 while computing block i2
        ulonglong2 hq[4];
        {
            const int ko = 4 * l;
            #pragma unroll
            for (int b = 0; b < 4; b++)
                hq[b] = __ldcg((const ulonglong2*)(hR + (hb0 + b) * U_ + ko));
        }
        #pragma unroll
        for (int i2 = 0; i2 < 4; i2++) {
            const int ko = 4 * l + 128 * i2;
            ulonglong2 hqn[4];
            if (i2 < 3) {
                const int kon = ko + 128;
                #pragma unroll
                for (int b = 0; b < 4; b++)
                    hqn[b] = __ldcg((const ulonglong2*)(hR + (hb0 + b) * U_ + kon));
            }
            #pragma unroll
            for (int c = 0; c < 12; c++) {
                ulonglong2 wq = *(const ulonglong2*)(wsq + c * U_ + ko);
                #pragma unroll
                for (int b = 0; b < 4; b++) {
                    FMA2(acc[b][c], hq[b].x, wq.x);
                    FMA2(acc[b][c], hq[b].y, wq.y);
                }
            }
            if (i2 < 3) {
                #pragma unroll
                for (int b = 0; b < 4; b++) hq[b] = hqn[b];
            }
        }

        float A[4][12];
        #pragma unroll
        for (int b = 0; b < 4; b++)
            #pragma unroll
            for (int c = 0; c < 12; c++) {
                float2 v = *reinterpret_cast<float2*>(&acc[b][c]);
                A[b][c] = v.x + v.y;
            }

        // compacted butterfly (verified rounds 4/7-10)
        #pragma unroll
        for (int b = 0; b < 4; b++)
            #pragma unroll
            for (int c = 0; c < 12; c++)
                A[b][c] += __shfl_xor_sync(0xffffffffu, A[b][c], 16);
        float B8[2][12];
        #pragma unroll
        for (int bl2 = 0; bl2 < 2; bl2++)
            #pragma unroll
            for (int c = 0; c < 12; c++) {
                float keep = bit3 ? A[2 + bl2][c] : A[bl2][c];
                float send = bit3 ? A[bl2][c]     : A[2 + bl2][c];
                B8[bl2][c] = keep + __shfl_xor_sync(0xffffffffu, send, 8);
            }
        float B4[12];
        #pragma unroll
        for (int c = 0; c < 12; c++) {
            float keep = bit2 ? B8[1][c] : B8[0][c];
            float send = bit2 ? B8[0][c] : B8[1][c];
            B4[c] = keep + __shfl_xor_sync(0xffffffffu, send, 4);
        }
        float B2[3][2];
        #pragma unroll
        for (int g = 0; g < 3; g++)
            #pragma unroll
            for (int j = 0; j < 2; j++) {
                float keep = bit1 ? B4[g * 4 + 2 + j] : B4[g * 4 + j];
                float send = bit1 ? B4[g * 4 + j]     : B4[g * 4 + 2 + j];
                B2[g][j] = keep + __shfl_xor_sync(0xffffffffu, send, 2);
            }
        float S[3];
        #pragma unroll
        for (int g = 0; g < 3; g++) {
            float keep = bit0 ? B2[g][1] : B2[g][0];
            float send = bit0 ? B2[g][0] : B2[g][1];
            S[g] = keep + __shfl_xor_sync(0xffffffffu, send, 1);
        }

        if (act) {
            float z  = fsig(xz + S[0] + bz);
            float r  = fsig(xr + S[1] + brr);
            float hh = ftanh(xh + r * (S[2] + bh));
            float hnew = z * hold + (1.f - z) * hh;
            __stcg(hW + gb * U_ + gu, hnew + 0.1f * (hold - hnew));  // zoneout
            out[((size_t)t * B_ + gb) * U_ + gu] = hnew;
        }

        if (act && t + 1 < T_) {
            const float* xwt = xw + ((size_t)(t + 1) * B_ + gb) * G3;
            xz = __ldg(xwt + gu);
            xr = __ldg(xwt + U_ + gu);
            xh = __ldg(xwt + 2 * U_ + gu);
        }
        if (t + 1 < T_) CLUSTER_SYNC();
    }
}

// ---------------- fp32 GEMM: 128x64 tile, 8x4 microtile, reg-staged prefetch --
__global__ void __launch_bounds__(256) gemm_kernel(
    const float* __restrict__ A0, const float* __restrict__ A1,
    const float* __restrict__ A2, const float* __restrict__ avec,
    int ia1, int ia2,
    const float* __restrict__ W, const float* __restrict__ bias,
    float* __restrict__ C, int M, int N, int K, int permA, int permC)
{
    __shared__ float As[16][132];   // [k][m], +4 pad
    __shared__ float Bs[16][64];

    const int tid = threadIdx.x;
    const int bm = blockIdx.x * 128;
    const int bn = blockIdx.y * 64;

    const int ra0 = tid >> 2;
    const int ra1 = ra0 + 64;
    const int ka  = (tid & 3) << 2;
    const int rb = tid >> 4, cb = (tid & 15) << 2;

    const float s1 = A1 ? avec[ia1] : 0.f;
    const float s2 = A2 ? avec[ia2] : 0.f;

    const int m0 = bm + ra0, m1 = bm + ra1;
    const size_t arow0 = permA ? ((size_t)(m0 & 31) * T_ + (m0 >> 5)) : (size_t)m0;
    const size_t arow1 = permA ? ((size_t)(m1 & 31) * T_ + (m1 >> 5)) : (size_t)m1;
    const float* Ap0a = A0 + arow0 * K + ka;
    const float* Ap0b = A0 + arow1 * K + ka;
    const float* Ap1a = A1 ? (A1 + arow0 * K + ka) : (const float*)0;
    const float* Ap1b = A1 ? (A1 + arow1 * K + ka) : (const float*)0;
    const float* Ap2a = A2 ? (A2 + arow0 * K + ka) : (const float*)0;
    const float* Ap2b = A2 ? (A2 + arow1 * K + ka) : (const float*)0;
    const float* Wp   = W + (size_t)rb * N + bn + cb;

    const int tm = (tid >> 4) << 3;
    const int tn = (tid & 15) << 2;

    ull acc2[8][2];
    #pragma unroll
    for (int i = 0; i < 8; i++) { acc2[i][0] = 0ull; acc2[i][1] = 0ull; }

    float4 av0 = *(const float4*)(Ap0a);
    float4 av1 = *(const float4*)(Ap0b);
    if (A1) {
        float4 t0 = *(const float4*)(Ap1a), t1 = *(const float4*)(Ap1b);
        av0.x += s1 * t0.x; av0.y += s1 * t0.y; av0.z += s1 * t0.z; av0.w += s1 * t0.w;
        av1.x += s1 * t1.x; av1.y += s1 * t1.y; av1.z += s1 * t1.z; av1.w += s1 * t1.w;
    }
    if (A2) {
        float4 t0 = *(const float4*)(Ap2a), t1 = *(const float4*)(Ap2b);
        av0.x += s2 * t0.x; av0.y += s2 * t0.y; av0.z += s2 * t0.z; av0.w += s2 * t0.w;
        av1.x += s2 * t1.x; av1.y += s2 * t1.y; av1.z += s2 * t1.z; av1.w += s2 * t1.w;
    }
    float4 bv = *(const float4*)(Wp);

    for (int k0 = 0; ; k0 += 16) {
        As[ka + 0][ra0] = av0.x; As[ka + 1][ra0] = av0.y;
        As[ka + 2][ra0] = av0.z; As[ka + 3][ra0] = av0.w;
        As[ka + 0][ra1] = av1.x; As[ka + 1][ra1] = av1.y;
        As[ka + 2][ra1] = av1.z; As[ka + 3][ra1] = av1.w;
        *(float4*)&Bs[rb][cb] = bv;
        __syncthreads();

        const bool last = (k0 + 16 >= K);
        if (!last) {
            const int kn = k0 + 16;
            av0 = *(const float4*)(Ap0a + kn);
            av1 = *(const float4*)(Ap0b + kn);
            if (A1) {
                float4 t0 = *(const float4*)(Ap1a + kn), t1 = *(const float4*)(Ap1b + kn);
                av0.x += s1 * t0.x; av0.y += s1 * t0.y; av0.z += s1 * t0.z; av0.w += s1 * t0.w;
                av1.x += s1 * t1.x; av1.y += s1 * t1.y; av1.z += s1 * t1.z; av1.w += s1 * t1.w;
            }
            if (A2) {
                float4 t0 = *(const float4*)(Ap2a + kn), t1 = *(const float4*)(Ap2b + kn);
                av0.x += s2 * t0.x; av0.y += s2 * t0.y; av0.z += s2 * t0.z; av0.w += s2 * t0.w;
                av1.x += s2 * t1.x; av1.y += s2 * t1.y; av1.z += s2 * t1.z; av1.w += s2 * t1.w;
            }
            bv = *(const float4*)(Wp + (size_t)kn * N);
        }

        #pragma unroll
        for (int kk = 0; kk < 16; kk++) {
            float4 aA = *(const float4*)&As[kk][tm];
            float4 aB = *(const float4*)&As[kk][tm + 4];
            ulonglong2 b2 = *(const ulonglong2*)&Bs[kk][tn];
            ull s_[8];
            SPLAT2(s_[0], aA.x); SPLAT2(s_[1], aA.y);
            SPLAT2(s_[2], aA.z); SPLAT2(s_[3], aA.w);
            SPLAT2(s_[4], aB.x); SPLAT2(s_[5], aB.y);
            SPLAT2(s_[6], aB.z); SPLAT2(s_[7], aB.w);
            #pragma unroll
            for (int i = 0; i < 8; i++) {
                FMA2(acc2[i][0], s_[i], b2.x);
                FMA2(acc2[i][1], s_[i], b2.y);
            }
        }
        __syncthreads();
        if (last) break;
    }

    #pragma unroll
    for (int i = 0; i < 8; i++) {
        int m = bm + tm + i;
        size_t crow = permC ? ((size_t)(m & 31) * T_ + (m >> 5)) : (size_t)m;
        float* cp = C + crow * N + bn + tn;
        #pragma unroll
        for (int jp = 0; jp < 2; jp++) {
            float2 v = *reinterpret_cast<float2*>(&acc2[i][jp]);
            cp[2 * jp + 0] = v.x + bias[bn + tn + 2 * jp + 0];
            cp[2 * jp + 1] = v.y + bias[bn + tn + 2 * jp + 1];
        }
    }
}

// ---------------- host orchestration -----------------------------------------
static void launch_scan(const float* R, const float* brec, const float* h0vec,
                        const float* xw, float* out, float* h0, float* h1)
{
    cudaLaunchConfig_t cfg = {};
    cfg.gridDim  = dim3(NCTA_SCAN, 1, 1);
    cfg.blockDim = dim3(256, 1, 1);
    cfg.dynamicSmemBytes = WS_BYTES;
    cudaLaunchAttribute attrs[1];
    attrs[0].id = cudaLaunchAttributeClusterDimension;
    attrs[0].val.clusterDim.x = CLUSTER;
    attrs[0].val.clusterDim.y = 1;
    attrs[0].val.clusterDim.z = 1;
    cfg.attrs = attrs;
    cfg.numAttrs = 1;
    cudaLaunchKernelEx(&cfg, scan_kernel, R, brec, h0vec, xw, out, h0, h1);
}

extern "C" void kernel_launch(void* const* d_in, const int* in_sizes, int n_in,
                              void* d_out, int out_size)
{
    const float* x   = (const float*)d_in[0];
    const float* k0  = (const float*)d_in[1];
    const float* r0  = (const float*)d_in[2];
    const float* b0  = (const float*)d_in[3];
    const float* ks  = (const float*)d_in[4];
    const float* rs  = (const float*)d_in[5];
    const float* bs  = (const float*)d_in[6];
    const float* h00 = (const float*)d_in[7];
    const float* h01 = (const float*)d_in[8];
    const float* h02 = (const float*)d_in[9];
    const float* a   = (const float*)d_in[10];
    const float* wd  = (const float*)d_in[11];
    const float* bd  = (const float*)d_in[12];

    float *xw, *out0, *p0, *p1, *hbase;
    cudaGetSymbolAddress((void**)&xw,    g_xw);
    cudaGetSymbolAddress((void**)&out0,  g_out0);
    cudaGetSymbolAddress((void**)&p0,    g_pred0);
    cudaGetSymbolAddress((void**)&p1,    g_pred1);
    cudaGetSymbolAddress((void**)&hbase, g_h);
    float* h0 = hbase;
    float* h1 = hbase + B_ * U_;

    // idempotent attribute setup (host-side, not stream-ordered)
    cudaFuncSetAttribute(scan_kernel,
                         cudaFuncAttributeMaxDynamicSharedMemorySize, WS_BYTES);
    cudaFuncSetAttribute(scan_kernel,
                         cudaFuncAttributeNonPortableClusterSizeAllowed, 1);

    const int M = B_ * T_;
    dim3 gridW(M / 128, G3 / 64);   // 256 x 24
    dim3 gridF(M / 128, D_ / 64);   // 256 x 4

    // ---- layer 0: xw = x @ k0 + b_in ----
    gemm_kernel<<<gridW, 256>>>(x, 0, 0, a, 0, 0, k0, b0, xw, M, G3, D_, 1, 0);
    launch_scan(r0, b0 + G3, h00, xw, out0, h0, h1);

    // ---- layer 1: input = out0 ----
    gemm_kernel<<<gridW, 256>>>(out0, 0, 0, a, 0, 0, ks, bs, xw, M, G3, U_, 0, 0);
    launch_scan(rs, bs + G3, h01, xw, p0, h0, h1);

    // ---- layer 2: input = out0 + a[0]*pred0 ----
    gemm_kernel<<<gridW, 256>>>(out0, p0, 0, a, 0, 0, ks, bs, xw, M, G3, U_, 0, 0);
    launch_scan(rs, bs + G3, h02, xw, p1, h0, h1);

    // ---- final: (out0 + a[1]*pred0 + a[2]*pred1) @ wd + bd -> [B,T,D] ----
    gemm_kernel<<<gridF, 256>>>(out0, p0, p1, a, 1, 2, wd, bd,
                                (float*)d_out, M, D_, U_, 0, 1);
}

// round 12
// speedup vs baseline: 1.1372x; 1.1372x over previous
#include <cuda_runtime.h>
#include <math.h>
#include <stdint.h>

#define B_  32
#define T_  1024
#define D_  256
#define U_  512
#define G3  1536          // 3*U
#define NCTA_SCAN 128
#define CLUSTER 16        // CTAs per cluster == per batch-group
#define NGRP 8            // 8 groups x 4 batches
#define GB   4            // batches per group
// dynamic SMEM: 96 gate-cols x 512 k weights + double-buffered group h
#define WS_FLOATS (96 * U_)
#define HBUF_FLOATS (GB * U_)
#define SMEM_BYTES ((WS_FLOATS + 2 * HBUF_FLOATS) * 4)   // 212992 B
#define TX_BYTES (CLUSTER * GB * 32u * 4u)               // 8192 B per step per CTA

typedef unsigned long long ull;

// packed fp32x2 FMA: d = a*b + d (elementwise on the two fp32 halves)
#define FMA2(d_, a_, b_) \
    asm("fma.rn.f32x2 %0, %1, %2, %3;" : "=l"(d_) : "l"(a_), "l"(b_), "l"(d_))
// splat a scalar float into both halves of a 64-bit packed reg
#define SPLAT2(d_, s_) \
    asm("mov.b64 %0, {%1, %1};" : "=l"(d_) : "r"(__float_as_uint(s_)))

// ---- mbarrier primitives (own-CTA) ----
#define MBARRIER_INIT(addr, cnt) \
    asm volatile("mbarrier.init.shared.b64 [%0], %1;" :: "r"(addr), "r"(cnt) : "memory")
#define MBARRIER_EXPECT_TX(addr, tx) \
    asm volatile("mbarrier.arrive.expect_tx.shared.b64 _, [%0], %1;" \
                 :: "r"(addr), "r"(tx) : "memory")
#define MBARRIER_WAIT_PARITY(addr, parity) do { \
    uint32_t _m = (addr), _p = (parity), _done; \
    asm volatile("{\n\t.reg .pred p;\n\t" \
        "mbarrier.try_wait.parity.acquire.cta.shared::cta.b64 p, [%1], %2;\n\t" \
        "selp.b32 %0, 1, 0, p;\n\t}" : "=r"(_done) : "r"(_m), "r"(_p) : "memory"); \
    if (!_done) { \
        asm volatile("{\n\t.reg .pred P1;\n\t" \
            "WAIT_LOOP_%=:\n\t" \
            "mbarrier.try_wait.parity.acquire.cta.shared::cta.b64 P1, [%0], %1, 0x989680;\n\t" \
            "@P1 bra.uni WAIT_DONE_%=;\n\t" \
            "bra.uni WAIT_LOOP_%=;\n\t" \
            "WAIT_DONE_%=:\n\t}" :: "r"(_m), "r"(_p) : "memory"); \
    } \
} while (0)

// cluster barrier — used ONCE at init (its L1D flush is why it can't be per-step)
#define CLUSTER_SYNC() do { \
    asm volatile("barrier.cluster.arrive.aligned;" ::: "memory"); \
    asm volatile("barrier.cluster.wait.aligned;"   ::: "memory"); \
} while (0)

__device__ __forceinline__ uint32_t smem_u32(const void* p) {
    uint32_t a;
    asm("{ .reg .u64 t; cvta.to.shared.u64 t, %1; cvt.u32.u64 %0, t; }"
        : "=r"(a) : "l"(p));
    return a;
}

// push one float into peer CTA's SMEM, counting bytes on peer's mbarrier
__device__ __forceinline__ void st_async_peer(uint32_t laddr, uint32_t lmbar,
                                              unsigned rank, float v) {
    uint32_t ra, rm;
    asm volatile("mapa.shared::cluster.u32 %0, %1, %2;" : "=r"(ra) : "r"(laddr), "r"(rank));
    asm volatile("mapa.shared::cluster.u32 %0, %1, %2;" : "=r"(rm) : "r"(lmbar), "r"(rank));
    asm volatile("st.async.shared::cluster.mbarrier::complete_tx::bytes.b32 [%0], %1, [%2];"
                 :: "r"(ra), "r"(__float_as_uint(v)), "r"(rm) : "memory");
}

// fast sigmoid / tanh via MUFU.EX2 + MUFU.RCP (~1-2e-7 rel err)
__device__ __forceinline__ float fsig(float x) {
    float e, r;
    asm("ex2.approx.f32 %0, %1;" : "=f"(e) : "f"(x * -1.442695041f));
    asm("rcp.approx.f32 %0, %1;" : "=f"(r) : "f"(1.0f + e));
    return r;
}
__device__ __forceinline__ float ftanh(float x) {
    float e, r;
    asm("ex2.approx.f32 %0, %1;" : "=f"(e) : "f"(x * -2.885390082f));
    asm("rcp.approx.f32 %0, %1;" : "=f"(r) : "f"(1.0f + e));
    return fmaf(2.0f, r, -1.0f);
}

// ---------------- scratch (device globals: allocation-free contract) ----------
__device__ float g_xw[(size_t)T_ * B_ * G3];     // [T,B,3U] gate pre-activations
__device__ float g_out0[(size_t)T_ * B_ * U_];   // layer-0 outputs [T,B,U]
__device__ float g_pred0[(size_t)T_ * B_ * U_];  // layer-1 outputs
__device__ float g_pred1[(size_t)T_ * B_ * U_];  // layer-2 outputs

// ---------------- persistent GRU scan: 8 clusters of 16 CTAs ------------------
// Cluster g owns batches 4g..4g+3; CTA owns 32 units (96 gate cols, SMEM).
// h replicated per CTA in SMEM (double buffered); per-step exchange via
// DSMEM st.async push + mbarrier tx-count. NO per-step L2 sync, NO L1 flush.
__global__ void __launch_bounds__(256, 1) scan_kernel(
    const float* __restrict__ R,
    const float* __restrict__ brec,
    const float* __restrict__ h0vec,
    const float* __restrict__ xw,
    float* __restrict__ out)
{
    extern __shared__ float ws[];           // [96][512] weights
    float* hb0 = ws + WS_FLOATS;            // h buffer parity 0: [4][512]
    float* hb1 = hb0 + HBUF_FLOATS;         // h buffer parity 1
    __shared__ __align__(8) ull mbars[2];

    const int tid = threadIdx.x;
    const int grp = blockIdx.x >> 4;        // cluster id 0..7
    const int cic = blockIdx.x & 15;        // rank within cluster
    const int u0c = cic * 32;               // first global unit owned

    // Preload 96 recurrent columns (verbatim round-11 mapping — verified).
    for (int idx = tid; idx < 3 * 32 * U_; idx += 256) {
        int uo = idx & 31;
        int g  = (idx >> 5) % 3;
        int k  = idx / 96;
        int c  = (uo >> 2) * 12 + g * 4 + (uo & 3);
        ws[c * U_ + k] = R[(size_t)k * G3 + g * U_ + u0c + uo];
    }
    // h init: full group h, local copy (h0 tiled over batches).
    for (int i = tid; i < GB * U_; i += 256)
        hb0[i] = h0vec[i & (U_ - 1)];
    if (tid == 0) {
        MBARRIER_INIT(smem_u32(&mbars[0]), 1u);
        MBARRIER_INIT(smem_u32(&mbars[1]), 1u);
    }
    CLUSTER_SYNC();   // once: mbarrier init + smem visible cluster-wide

    const int w  = tid >> 5, l = tid & 31;
    const float* wsq = ws + w * 12 * U_;    // this warp's 12 cols
    const int lb = l >> 2, uj = l & 3;
    const int gb = grp * GB + lb;           // global batch (act lanes)
    const int gu = u0c + w * 4 + uj;        // global unit (act lanes)
    const bool act = (l < 16);
    const unsigned bit0 = l & 1, bit1 = (l >> 1) & 1;
    const unsigned bit2 = (l >> 2) & 1, bit3 = (l >> 3) & 1;

    // store-lane mapping: lane pushes value of lane (l&15) to 8 peers
    const int sl  = l & 15;
    const int soff = ((sl >> 2) * U_ + (u0c + w * 4 + (sl & 3))) * 4;  // byte off in hbuf
    const unsigned pbase = (l >> 4) * 8;    // peers 0-7 or 8-15
    const uint32_t h0a = smem_u32(hb0), h1a = smem_u32(hb1);
    const uint32_t mb0 = smem_u32(&mbars[0]), mb1 = smem_u32(&mbars[1]);

    float bz = 0.f, brr = 0.f, bh = 0.f;
    if (act) {
        bz  = brec[gu];
        brr = brec[U_ + gu];
        bh  = brec[2 * U_ + gu];
    }

    float xz = 0.f, xr = 0.f, xh = 0.f;
    if (act) {
        const float* xwt = xw + (size_t)gb * G3;
        xz = __ldg(xwt + gu);
        xr = __ldg(xwt + U_ + gu);
        xh = __ldg(xwt + 2 * U_ + gu);
    }

    for (int t = 0; t < T_; t++) {
        const float*   hR  = (t & 1) ? hb1 : hb0;          // read buffer
        const uint32_t hWa = ((t & 1) ? h0a : h1a) + soff; // write byte-addr
        const uint32_t mba = (t & 1) ? mb1 : mb0;          // this step's barrier
        const bool     more = (t + 1 < T_);

        // arm this step's barrier early (off critical path)
        if (tid == 0 && more) MBARRIER_EXPECT_TX(mba, TX_BYTES);

        float hold = act ? hR[lb * U_ + gu] : 0.f;

        ull acc[4][12];
        #pragma unroll
        for (int b = 0; b < 4; b++)
            #pragma unroll
            for (int c = 0; c < 12; c++) acc[b][c] = 0ull;

        #pragma unroll
        for (int i2 = 0; i2 < 4; i2++) {
            const int ko = 4 * l + 128 * i2;
            ulonglong2 hq[4];
            #pragma unroll
            for (int b = 0; b < 4; b++)
                hq[b] = *(const ulonglong2*)(hR + b * U_ + ko);   // local LDS
            #pragma unroll
            for (int c = 0; c < 12; c++) {
                ulonglong2 wq = *(const ulonglong2*)(wsq + c * U_ + ko);
                #pragma unroll
                for (int b = 0; b < 4; b++) {
                    FMA2(acc[b][c], hq[b].x, wq.x);
                    FMA2(acc[b][c], hq[b].y, wq.y);
                }
            }
        }

        float A[4][12];
        #pragma unroll
        for (int b = 0; b < 4; b++)
            #pragma unroll
            for (int c = 0; c < 12; c++) {
                float2 v = *reinterpret_cast<float2*>(&acc[b][c]);
                A[b][c] = v.x + v.y;
            }

        // compacted butterfly (verified rounds 4/7-11)
        #pragma unroll
        for (int b = 0; b < 4; b++)
            #pragma unroll
            for (int c = 0; c < 12; c++)
                A[b][c] += __shfl_xor_sync(0xffffffffu, A[b][c], 16);
        float B8[2][12];
        #pragma unroll
        for (int b2 = 0; b2 < 2; b2++)
            #pragma unroll
            for (int c = 0; c < 12; c++) {
                float keep = bit3 ? A[2 + b2][c] : A[b2][c];
                float send = bit3 ? A[b2][c]     : A[2 + b2][c];
                B8[b2][c] = keep + __shfl_xor_sync(0xffffffffu, send, 8);
            }
        float B4[12];
        #pragma unroll
        for (int c = 0; c < 12; c++) {
            float keep = bit2 ? B8[1][c] : B8[0][c];
            float send = bit2 ? B8[0][c] : B8[1][c];
            B4[c] = keep + __shfl_xor_sync(0xffffffffu, send, 4);
        }
        float B2[3][2];
        #pragma unroll
        for (int g = 0; g < 3; g++)
            #pragma unroll
            for (int j = 0; j < 2; j++) {
                float keep = bit1 ? B4[g * 4 + 2 + j] : B4[g * 4 + j];
                float send = bit1 ? B4[g * 4 + j]     : B4[g * 4 + 2 + j];
                B2[g][j] = keep + __shfl_xor_sync(0xffffffffu, send, 2);
            }
        float S[3];
        #pragma unroll
        for (int g = 0; g < 3; g++) {
            float keep = bit0 ? B2[g][1] : B2[g][0];
            float send = bit0 ? B2[g][0] : B2[g][1];
            S[g] = keep + __shfl_xor_sync(0xffffffffu, send, 1);
        }

        float carried = 0.f;
        if (act) {
            float z  = fsig(xz + S[0] + bz);
            float r  = fsig(xr + S[1] + brr);
            float hh = ftanh(xh + r * (S[2] + bh));
            float hnew = z * hold + (1.f - z) * hh;
            carried = hnew + 0.1f * (hold - hnew);        // zoneout carry
            out[((size_t)t * B_ + gb) * U_ + gu] = hnew;
        }

        if (more) {
            // broadcast carried value of lane (l&15) to this lane
            float cv = __shfl_sync(0xffffffffu, carried, sl);
            // push to 8 peer CTAs (other 8 handled by partner half-warp)
            #pragma unroll
            for (int pp = 0; pp < 8; pp++)
                st_async_peer(hWa, mba, pbase + pp, cv);

            // prefetch next step's xw while stores drain
            if (act) {
                const float* xwt = xw + ((size_t)(t + 1) * B_ + gb) * G3;
                xz = __ldg(xwt + gu);
                xr = __ldg(xwt + U_ + gu);
                xh = __ldg(xwt + 2 * U_ + gu);
            }
            MBARRIER_WAIT_PARITY(mba, (unsigned)((t >> 1) & 1));
        }
    }
}

// ---------------- fp32 GEMM: 128x64 tile, 8x4 microtile, reg-staged prefetch --
__global__ void __launch_bounds__(256) gemm_kernel(
    const float* __restrict__ A0, const float* __restrict__ A1,
    const float* __restrict__ A2, const float* __restrict__ avec,
    int ia1, int ia2,
    const float* __restrict__ W, const float* __restrict__ bias,
    float* __restrict__ C, int M, int N, int K, int permA, int permC)
{
    __shared__ float As[16][132];   // [k][m], +4 pad
    __shared__ float Bs[16][64];

    const int tid = threadIdx.x;
    const int bm = blockIdx.x * 128;
    const int bn = blockIdx.y * 64;

    const int ra0 = tid >> 2;
    const int ra1 = ra0 + 64;
    const int ka  = (tid & 3) << 2;
    const int rb = tid >> 4, cb = (tid & 15) << 2;

    const float s1 = A1 ? avec[ia1] : 0.f;
    const float s2 = A2 ? avec[ia2] : 0.f;

    const int m0 = bm + ra0, m1 = bm + ra1;
    const size_t arow0 = permA ? ((size_t)(m0 & 31) * T_ + (m0 >> 5)) : (size_t)m0;
    const size_t arow1 = permA ? ((size_t)(m1 & 31) * T_ + (m1 >> 5)) : (size_t)m1;
    const float* Ap0a = A0 + arow0 * K + ka;
    const float* Ap0b = A0 + arow1 * K + ka;
    const float* Ap1a = A1 ? (A1 + arow0 * K + ka) : (const float*)0;
    const float* Ap1b = A1 ? (A1 + arow1 * K + ka) : (const float*)0;
    const float* Ap2a = A2 ? (A2 + arow0 * K + ka) : (const float*)0;
    const float* Ap2b = A2 ? (A2 + arow1 * K + ka) : (const float*)0;
    const float* Wp   = W + (size_t)rb * N + bn + cb;

    const int tm = (tid >> 4) << 3;
    const int tn = (tid & 15) << 2;

    ull acc2[8][2];
    #pragma unroll
    for (int i = 0; i < 8; i++) { acc2[i][0] = 0ull; acc2[i][1] = 0ull; }

    float4 av0 = *(const float4*)(Ap0a);
    float4 av1 = *(const float4*)(Ap0b);
    if (A1) {
        float4 t0 = *(const float4*)(Ap1a), t1 = *(const float4*)(Ap1b);
        av0.x += s1 * t0.x; av0.y += s1 * t0.y; av0.z += s1 * t0.z; av0.w += s1 * t0.w;
        av1.x += s1 * t1.x; av1.y += s1 * t1.y; av1.z += s1 * t1.z; av1.w += s1 * t1.w;
    }
    if (A2) {
        float4 t0 = *(const float4*)(Ap2a), t1 = *(const float4*)(Ap2b);
        av0.x += s2 * t0.x; av0.y += s2 * t0.y; av0.z += s2 * t0.z; av0.w += s2 * t0.w;
        av1.x += s2 * t1.x; av1.y += s2 * t1.y; av1.z += s2 * t1.z; av1.w += s2 * t1.w;
    }
    float4 bv = *(const float4*)(Wp);

    for (int k0 = 0; ; k0 += 16) {
        As[ka + 0][ra0] = av0.x; As[ka + 1][ra0] = av0.y;
        As[ka + 2][ra0] = av0.z; As[ka + 3][ra0] = av0.w;
        As[ka + 0][ra1] = av1.x; As[ka + 1][ra1] = av1.y;
        As[ka + 2][ra1] = av1.z; As[ka + 3][ra1] = av1.w;
        *(float4*)&Bs[rb][cb] = bv;
        __syncthreads();

        const bool last = (k0 + 16 >= K);
        if (!last) {
            const int kn = k0 + 16;
            av0 = *(const float4*)(Ap0a + kn);
            av1 = *(const float4*)(Ap0b + kn);
            if (A1) {
                float4 t0 = *(const float4*)(Ap1a + kn), t1 = *(const float4*)(Ap1b + kn);
                av0.x += s1 * t0.x; av0.y += s1 * t0.y; av0.z += s1 * t0.z; av0.w += s1 * t0.w;
                av1.x += s1 * t1.x; av1.y += s1 * t1.y; av1.z += s1 * t1.z; av1.w += s1 * t1.w;
            }
            if (A2) {
                float4 t0 = *(const float4*)(Ap2a + kn), t1 = *(const float4*)(Ap2b + kn);
                av0.x += s2 * t0.x; av0.y += s2 * t0.y; av0.z += s2 * t0.z; av0.w += s2 * t0.w;
                av1.x += s2 * t1.x; av1.y += s2 * t1.y; av1.z += s2 * t1.z; av1.w += s2 * t1.w;
            }
            bv = *(const float4*)(Wp + (size_t)kn * N);
        }

        #pragma unroll
        for (int kk = 0; kk < 16; kk++) {
            float4 aA = *(const float4*)&As[kk][tm];
            float4 aB = *(const float4*)&As[kk][tm + 4];
            ulonglong2 b2 = *(const ulonglong2*)&Bs[kk][tn];
            ull s_[8];
            SPLAT2(s_[0], aA.x); SPLAT2(s_[1], aA.y);
            SPLAT2(s_[2], aA.z); SPLAT2(s_[3], aA.w);
            SPLAT2(s_[4], aB.x); SPLAT2(s_[5], aB.y);
            SPLAT2(s_[6], aB.z); SPLAT2(s_[7], aB.w);
            #pragma unroll
            for (int i = 0; i < 8; i++) {
                FMA2(acc2[i][0], s_[i], b2.x);
                FMA2(acc2[i][1], s_[i], b2.y);
            }
        }
        __syncthreads();
        if (last) break;
    }

    #pragma unroll
    for (int i = 0; i < 8; i++) {
        int m = bm + tm + i;
        size_t crow = permC ? ((size_t)(m & 31) * T_ + (m >> 5)) : (size_t)m;
        float* cp = C + crow * N + bn + tn;
        #pragma unroll
        for (int jp = 0; jp < 2; jp++) {
            float2 v = *reinterpret_cast<float2*>(&acc2[i][jp]);
            cp[2 * jp + 0] = v.x + bias[bn + tn + 2 * jp + 0];
            cp[2 * jp + 1] = v.y + bias[bn + tn + 2 * jp + 1];
        }
    }
}

// ---------------- host orchestration -----------------------------------------
static void launch_scan(const float* R, const float* brec, const float* h0vec,
                        const float* xw, float* out)
{
    cudaLaunchConfig_t cfg = {};
    cfg.gridDim  = dim3(NCTA_SCAN, 1, 1);
    cfg.blockDim = dim3(256, 1, 1);
    cfg.dynamicSmemBytes = SMEM_BYTES;
    cudaLaunchAttribute attrs[1];
    attrs[0].id = cudaLaunchAttributeClusterDimension;
    attrs[0].val.clusterDim.x = CLUSTER;
    attrs[0].val.clusterDim.y = 1;
    attrs[0].val.clusterDim.z = 1;
    cfg.attrs = attrs;
    cfg.numAttrs = 1;
    cudaLaunchKernelEx(&cfg, scan_kernel, R, brec, h0vec, xw, out);
}

extern "C" void kernel_launch(void* const* d_in, const int* in_sizes, int n_in,
                              void* d_out, int out_size)
{
    const float* x   = (const float*)d_in[0];
    const float* k0  = (const float*)d_in[1];
    const float* r0  = (const float*)d_in[2];
    const float* b0  = (const float*)d_in[3];
    const float* ks  = (const float*)d_in[4];
    const float* rs  = (const float*)d_in[5];
    const float* bs  = (const float*)d_in[6];
    const float* h00 = (const float*)d_in[7];
    const float* h01 = (const float*)d_in[8];
    const float* h02 = (const float*)d_in[9];
    const float* a   = (const float*)d_in[10];
    const float* wd  = (const float*)d_in[11];
    const float* bd  = (const float*)d_in[12];

    float *xw, *out0, *p0, *p1;
    cudaGetSymbolAddress((void**)&xw,   g_xw);
    cudaGetSymbolAddress((void**)&out0, g_out0);
    cudaGetSymbolAddress((void**)&p0,   g_pred0);
    cudaGetSymbolAddress((void**)&p1,   g_pred1);

    // idempotent attribute setup (host-side, not stream-ordered)
    cudaFuncSetAttribute(scan_kernel,
                         cudaFuncAttributeMaxDynamicSharedMemorySize, SMEM_BYTES);
    cudaFuncSetAttribute(scan_kernel,
                         cudaFuncAttributeNonPortableClusterSizeAllowed, 1);

    const int M = B_ * T_;
    dim3 gridW(M / 128, G3 / 64);   // 256 x 24
    dim3 gridF(M / 128, D_ / 64);   // 256 x 4

    // ---- layer 0: xw = x @ k0 + b_in ----
    gemm_kernel<<<gridW, 256>>>(x, 0, 0, a, 0, 0, k0, b0, xw, M, G3, D_, 1, 0);
    launch_scan(r0, b0 + G3, h00, xw, out0);

    // ---- layer 1: input = out0 ----
    gemm_kernel<<<gridW, 256>>>(out0, 0, 0, a, 0, 0, ks, bs, xw, M, G3, U_, 0, 0);
    launch_scan(rs, bs + G3, h01, xw, p0);

    // ---- layer 2: input = out0 + a[0]*pred0 ----
    gemm_kernel<<<gridW, 256>>>(out0, p0, 0, a, 0, 0, ks, bs, xw, M, G3, U_, 0, 0);
    launch_scan(rs, bs + G3, h02, xw, p1);

    // ---- final: (out0 + a[1]*pred0 + a[2]*pred1) @ wd + bd -> [B,T,D] ----
    gemm_kernel<<<gridF, 256>>>(out0, p0, p1, a, 1, 2, wd, bd,
                                (float*)d_out, M, D_, U_, 0, 1);
}

// round 13
// speedup vs baseline: 1.2037x; 1.0584x over previous
#include <cuda_runtime.h>
#include <math.h>
#include <stdint.h>

#define B_  32
#define T_  1024
#define D_  256
#define U_  512
#define G3  1536          // 3*U
#define NCTA_SCAN 128
#define CLUSTER 16        // CTAs per cluster == per batch-group
#define NGRP 8            // 8 groups x 4 batches
#define GB   4            // batches per group
// dynamic SMEM: 96 gate-cols x 512 k weights + double-buffered slotted group h
#define WS_FLOATS (96 * U_)
#define HBUF_FLOATS (CLUSTER * 128)                      // [16 ranks][4b x 32u]
#define SMEM_BYTES ((WS_FLOATS + 2 * HBUF_FLOATS) * 4)   // 212992 B
#define TX_BYTES (CLUSTER * 512u)                        // 16 x 512B per step

typedef unsigned long long ull;

// packed fp32x2 FMA: d = a*b + d (elementwise on the two fp32 halves)
#define FMA2(d_, a_, b_) \
    asm("fma.rn.f32x2 %0, %1, %2, %3;" : "=l"(d_) : "l"(a_), "l"(b_), "l"(d_))
// splat a scalar float into both halves of a 64-bit packed reg
#define SPLAT2(d_, s_) \
    asm("mov.b64 %0, {%1, %1};" : "=l"(d_) : "r"(__float_as_uint(s_)))

// ---- mbarrier primitives ----
#define MBARRIER_INIT(addr, cnt) \
    asm volatile("mbarrier.init.shared.b64 [%0], %1;" :: "r"(addr), "r"(cnt) : "memory")
#define MBARRIER_EXPECT_TX(addr, tx) \
    asm volatile("mbarrier.arrive.expect_tx.shared.b64 _, [%0], %1;" \
                 :: "r"(addr), "r"(tx) : "memory")
#define MBARRIER_WAIT_PARITY(addr, parity) do { \
    uint32_t _m = (addr), _p = (parity), _done; \
    asm volatile("{\n\t.reg .pred p;\n\t" \
        "mbarrier.try_wait.parity.acquire.cta.shared::cta.b64 p, [%1], %2;\n\t" \
        "selp.b32 %0, 1, 0, p;\n\t}" : "=r"(_done) : "r"(_m), "r"(_p) : "memory"); \
    if (!_done) { \
        asm volatile("{\n\t.reg .pred P1;\n\t" \
            "WAIT_LOOP_%=:\n\t" \
            "mbarrier.try_wait.parity.acquire.cta.shared::cta.b64 P1, [%0], %1, 0x989680;\n\t" \
            "@P1 bra.uni WAIT_DONE_%=;\n\t" \
            "bra.uni WAIT_LOOP_%=;\n\t" \
            "WAIT_DONE_%=:\n\t}" :: "r"(_m), "r"(_p) : "memory"); \
    } \
} while (0)

// cluster barrier — used ONCE at init (per-step use flushes L1D: round-11 lesson)
#define CLUSTER_SYNC() do { \
    asm volatile("barrier.cluster.arrive.aligned;" ::: "memory"); \
    asm volatile("barrier.cluster.wait.aligned;"   ::: "memory"); \
} while (0)

__device__ __forceinline__ uint32_t smem_u32(const void* p) {
    uint32_t a;
    asm("{ .reg .u64 t; cvta.to.shared.u64 t, %1; cvt.u32.u64 %0, t; }"
        : "=r"(a) : "l"(p));
    return a;
}
__device__ __forceinline__ uint32_t mapa_rank(uint32_t laddr, unsigned rank) {
    uint32_t ra;
    asm("mapa.shared::cluster.u32 %0, %1, %2;" : "=r"(ra) : "r"(laddr), "r"(rank));
    return ra;
}

// fast sigmoid / tanh via MUFU.EX2 + MUFU.RCP (~1-2e-7 rel err)
__device__ __forceinline__ float fsig(float x) {
    float e, r;
    asm("ex2.approx.f32 %0, %1;" : "=f"(e) : "f"(x * -1.442695041f));
    asm("rcp.approx.f32 %0, %1;" : "=f"(r) : "f"(1.0f + e));
    return r;
}
__device__ __forceinline__ float ftanh(float x) {
    float e, r;
    asm("ex2.approx.f32 %0, %1;" : "=f"(e) : "f"(x * -2.885390082f));
    asm("rcp.approx.f32 %0, %1;" : "=f"(r) : "f"(1.0f + e));
    return fmaf(2.0f, r, -1.0f);
}

// ---------------- scratch (device globals: allocation-free contract) ----------
__device__ float g_xw[(size_t)T_ * B_ * G3];     // [T,B,3U] gate pre-activations
__device__ float g_out0[(size_t)T_ * B_ * U_];   // layer-0 outputs [T,B,U]
__device__ float g_pred0[(size_t)T_ * B_ * U_];  // layer-1 outputs
__device__ float g_pred1[(size_t)T_ * B_ * U_];  // layer-2 outputs

// ---------------- persistent GRU scan: 8 clusters of 16 CTAs ------------------
// h replicated per CTA in SMEM, slot-major [rank][4b][32u], double buffered.
// Per-step exchange: STS to 512B staging -> 16 cp.async.bulk (one per peer)
// with mbarrier complete_tx. No L2 sync, no L1 flush, 16 transactions/step.
__global__ void __launch_bounds__(256, 1) scan_kernel(
    const float* __restrict__ R,
    const float* __restrict__ brec,
    const float* __restrict__ h0vec,
    const float* __restrict__ xw,
    float* __restrict__ out)
{
    extern __shared__ float ws[];           // [96][512] weights
    float* hb0 = ws + WS_FLOATS;            // h parity 0: [16][128]
    float* hb1 = hb0 + HBUF_FLOATS;         // h parity 1
    __shared__ __align__(16) float staging[2][128];
    __shared__ __align__(8) ull mbars[2];

    const int tid = threadIdx.x;
    const int grp = blockIdx.x >> 4;        // cluster id 0..7
    const int cic = blockIdx.x & 15;        // rank within cluster
    const int u0c = cic * 32;               // first global unit owned

    // Preload 96 recurrent columns (verbatim round-11/12 mapping — verified).
    for (int idx = tid; idx < 3 * 32 * U_; idx += 256) {
        int uo = idx & 31;
        int g  = (idx >> 5) % 3;
        int k  = idx / 96;
        int c  = (uo >> 2) * 12 + g * 4 + (uo & 3);
        ws[c * U_ + k] = R[(size_t)k * G3 + g * U_ + u0c + uo];
    }
    // h init, slotted: hb0[s*128 + b*32 + uo] = h0[s*32+uo]
    for (int i = tid; i < HBUF_FLOATS; i += 256) {
        int s = i >> 7, uo = i & 31;
        hb0[i] = h0vec[s * 32 + uo];
    }
    if (tid == 0) {
        MBARRIER_INIT(smem_u32(&mbars[0]), 1u);
        MBARRIER_INIT(smem_u32(&mbars[1]), 1u);
    }
    CLUSTER_SYNC();   // once: mbarrier init + smem visible cluster-wide

    const int w  = tid >> 5, l = tid & 31;
    const float* wsq = ws + w * 12 * U_;    // this warp's 12 cols
    const int lb = l >> 2, uj = l & 3;
    const int gb = grp * GB + lb;           // global batch (act lanes)
    const int gu = u0c + w * 4 + uj;        // global unit (act lanes)
    const bool act = (l < 16);
    const unsigned bit0 = l & 1, bit1 = (l >> 1) & 1;
    const unsigned bit2 = (l >> 2) & 1, bit3 = (l >> 3) & 1;

    const uint32_t mb0 = smem_u32(&mbars[0]), mb1 = smem_u32(&mbars[1]);
    const uint32_t stg0 = smem_u32(&staging[0][0]);
    const uint32_t stg1 = smem_u32(&staging[1][0]);

    // issuing lanes: warp 0, lane l -> peer rank l. Hoist mapa'd addresses.
    uint32_t dst0 = 0, dst1 = 0, rmb0 = 0, rmb1 = 0;
    if (w == 0 && l < CLUSTER) {
        uint32_t slotoff = (uint32_t)(cic * 128 * 4);    // our slot in peer hbuf
        dst0 = mapa_rank(smem_u32(hb0) + slotoff, (unsigned)l);
        dst1 = mapa_rank(smem_u32(hb1) + slotoff, (unsigned)l);
        rmb0 = mapa_rank(mb0, (unsigned)l);
        rmb1 = mapa_rank(mb1, (unsigned)l);
    }

    float bz = 0.f, brr = 0.f, bh = 0.f;
    if (act) {
        bz  = brec[gu];
        brr = brec[U_ + gu];
        bh  = brec[2 * U_ + gu];
    }

    float xz = 0.f, xr = 0.f, xh = 0.f;
    if (act) {
        const float* xwt = xw + (size_t)gb * G3;
        xz = __ldg(xwt + gu);
        xr = __ldg(xwt + U_ + gu);
        xh = __ldg(xwt + 2 * U_ + gu);
    }

    const int hold_idx = cic * 128 + lb * 32 + w * 4 + uj;
    const int stg_idx  = lb * 32 + w * 4 + uj;
    const int lko = 4 * (l & 7);             // within-slot float offset
    const int lsl = l >> 3;                  // slot sub-index (0..3)

    for (int t = 0; t < T_; t++) {
        const float*   hR  = (t & 1) ? hb1 : hb0;         // read buffer
        const uint32_t mba = (t & 1) ? mb1 : mb0;         // this step's barrier
        const bool     more = (t + 1 < T_);

        if (tid == 0 && more) MBARRIER_EXPECT_TX(mba, TX_BYTES);

        float hold = act ? hR[hold_idx] : 0.f;

        ull acc[4][12];
        #pragma unroll
        for (int b = 0; b < 4; b++)
            #pragma unroll
            for (int c = 0; c < 12; c++) acc[b][c] = 0ull;

        #pragma unroll
        for (int i2 = 0; i2 < 4; i2++) {
            const int slot = lsl + 4 * i2;                // 0..15
            const int hoff = slot * 128 + lko;
            ulonglong2 hq[4];
            #pragma unroll
            for (int b = 0; b < 4; b++)
                hq[b] = *(const ulonglong2*)(hR + hoff + b * 32);   // local LDS
            const int ko = 4 * l + 128 * i2;              // k index for weights
            #pragma unroll
            for (int c = 0; c < 12; c++) {
                ulonglong2 wq = *(const ulonglong2*)(wsq + c * U_ + ko);
                #pragma unroll
                for (int b = 0; b < 4; b++) {
                    FMA2(acc[b][c], hq[b].x, wq.x);
                    FMA2(acc[b][c], hq[b].y, wq.y);
                }
            }
        }

        float A[4][12];
        #pragma unroll
        for (int b = 0; b < 4; b++)
            #pragma unroll
            for (int c = 0; c < 12; c++) {
                float2 v = *reinterpret_cast<float2*>(&acc[b][c]);
                A[b][c] = v.x + v.y;
            }

        // compacted butterfly (verified rounds 4/7-12)
        #pragma unroll
        for (int b = 0; b < 4; b++)
            #pragma unroll
            for (int c = 0; c < 12; c++)
                A[b][c] += __shfl_xor_sync(0xffffffffu, A[b][c], 16);
        float B8[2][12];
        #pragma unroll
        for (int b2 = 0; b2 < 2; b2++)
            #pragma unroll
            for (int c = 0; c < 12; c++) {
                float keep = bit3 ? A[2 + b2][c] : A[b2][c];
                float send = bit3 ? A[b2][c]     : A[2 + b2][c];
                B8[b2][c] = keep + __shfl_xor_sync(0xffffffffu, send, 8);
            }
        float B4[12];
        #pragma unroll
        for (int c = 0; c < 12; c++) {
            float keep = bit2 ? B8[1][c] : B8[0][c];
            float send = bit2 ? B8[0][c] : B8[1][c];
            B4[c] = keep + __shfl_xor_sync(0xffffffffu, send, 4);
        }
        float B2[3][2];
        #pragma unroll
        for (int g = 0; g < 3; g++)
            #pragma unroll
            for (int j = 0; j < 2; j++) {
                float keep = bit1 ? B4[g * 4 + 2 + j] : B4[g * 4 + j];
                float send = bit1 ? B4[g * 4 + j]     : B4[g * 4 + 2 + j];
                B2[g][j] = keep + __shfl_xor_sync(0xffffffffu, send, 2);
            }
        float S[3];
        #pragma unroll
        for (int g = 0; g < 3; g++) {
            float keep = bit0 ? B2[g][1] : B2[g][0];
            float send = bit0 ? B2[g][0] : B2[g][1];
            S[g] = keep + __shfl_xor_sync(0xffffffffu, send, 1);
        }

        if (act) {
            float z  = fsig(xz + S[0] + bz);
            float r  = fsig(xr + S[1] + brr);
            float hh = ftanh(xh + r * (S[2] + bh));
            float hnew = z * hold + (1.f - z) * hh;
            out[((size_t)t * B_ + gb) * U_ + gu] = hnew;
            staging[t & 1][stg_idx] = hnew + 0.1f * (hold - hnew);  // zoneout
        }

        if (more) {
            __syncthreads();                  // all act lanes' STS done
            if (w == 0 && l < CLUSTER) {
                asm volatile("fence.proxy.async.shared::cta;" ::: "memory");
                uint32_t dst = (t & 1) ? dst0 : dst1;     // write opposite buffer
                uint32_t rmb = (t & 1) ? rmb1 : rmb0;     // step-t barrier, remote
                uint32_t src = (t & 1) ? stg1 : stg0;
                asm volatile(
                    "cp.async.bulk.shared::cluster.shared::cta.mbarrier::complete_tx::bytes "
                    "[%0], [%1], %2, [%3];"
                    :: "r"(dst), "r"(src), "r"(512u), "r"(rmb) : "memory");
            }
            // prefetch next step's xw while copies fly
            if (act) {
                const float* xwt = xw + ((size_t)(t + 1) * B_ + gb) * G3;
                xz = __ldg(xwt + gu);
                xr = __ldg(xwt + U_ + gu);
                xh = __ldg(xwt + 2 * U_ + gu);
            }
            MBARRIER_WAIT_PARITY(mba, (unsigned)((t >> 1) & 1));
        }
    }
}

// ---------------- fp32 GEMM: 128x64 tile, 8x4 microtile, reg-staged prefetch --
__global__ void __launch_bounds__(256) gemm_kernel(
    const float* __restrict__ A0, const float* __restrict__ A1,
    const float* __restrict__ A2, const float* __restrict__ avec,
    int ia1, int ia2,
    const float* __restrict__ W, const float* __restrict__ bias,
    float* __restrict__ C, int M, int N, int K, int permA, int permC)
{
    __shared__ float As[16][132];   // [k][m], +4 pad
    __shared__ float Bs[16][64];

    const int tid = threadIdx.x;
    const int bm = blockIdx.x * 128;
    const int bn = blockIdx.y * 64;

    const int ra0 = tid >> 2;
    const int ra1 = ra0 + 64;
    const int ka  = (tid & 3) << 2;
    const int rb = tid >> 4, cb = (tid & 15) << 2;

    const float s1 = A1 ? avec[ia1] : 0.f;
    const float s2 = A2 ? avec[ia2] : 0.f;

    const int m0 = bm + ra0, m1 = bm + ra1;
    const size_t arow0 = permA ? ((size_t)(m0 & 31) * T_ + (m0 >> 5)) : (size_t)m0;
    const size_t arow1 = permA ? ((size_t)(m1 & 31) * T_ + (m1 >> 5)) : (size_t)m1;
    const float* Ap0a = A0 + arow0 * K + ka;
    const float* Ap0b = A0 + arow1 * K + ka;
    const float* Ap1a = A1 ? (A1 + arow0 * K + ka) : (const float*)0;
    const float* Ap1b = A1 ? (A1 + arow1 * K + ka) : (const float*)0;
    const float* Ap2a = A2 ? (A2 + arow0 * K + ka) : (const float*)0;
    const float* Ap2b = A2 ? (A2 + arow1 * K + ka) : (const float*)0;
    const float* Wp   = W + (size_t)rb * N + bn + cb;

    const int tm = (tid >> 4) << 3;
    const int tn = (tid & 15) << 2;

    ull acc2[8][2];
    #pragma unroll
    for (int i = 0; i < 8; i++) { acc2[i][0] = 0ull; acc2[i][1] = 0ull; }

    float4 av0 = *(const float4*)(Ap0a);
    float4 av1 = *(const float4*)(Ap0b);
    if (A1) {
        float4 t0 = *(const float4*)(Ap1a), t1 = *(const float4*)(Ap1b);
        av0.x += s1 * t0.x; av0.y += s1 * t0.y; av0.z += s1 * t0.z; av0.w += s1 * t0.w;
        av1.x += s1 * t1.x; av1.y += s1 * t1.y; av1.z += s1 * t1.z; av1.w += s1 * t1.w;
    }
    if (A2) {
        float4 t0 = *(const float4*)(Ap2a), t1 = *(const float4*)(Ap2b);
        av0.x += s2 * t0.x; av0.y += s2 * t0.y; av0.z += s2 * t0.z; av0.w += s2 * t0.w;
        av1.x += s2 * t1.x; av1.y += s2 * t1.y; av1.z += s2 * t1.z; av1.w += s2 * t1.w;
    }
    float4 bv = *(const float4*)(Wp);

    for (int k0 = 0; ; k0 += 16) {
        As[ka + 0][ra0] = av0.x; As[ka + 1][ra0] = av0.y;
        As[ka + 2][ra0] = av0.z; As[ka + 3][ra0] = av0.w;
        As[ka + 0][ra1] = av1.x; As[ka + 1][ra1] = av1.y;
        As[ka + 2][ra1] = av1.z; As[ka + 3][ra1] = av1.w;
        *(float4*)&Bs[rb][cb] = bv;
        __syncthreads();

        const bool last = (k0 + 16 >= K);
        if (!last) {
            const int kn = k0 + 16;
            av0 = *(const float4*)(Ap0a + kn);
            av1 = *(const float4*)(Ap0b + kn);
            if (A1) {
                float4 t0 = *(const float4*)(Ap1a + kn), t1 = *(const float4*)(Ap1b + kn);
                av0.x += s1 * t0.x; av0.y += s1 * t0.y; av0.z += s1 * t0.z; av0.w += s1 * t0.w;
                av1.x += s1 * t1.x; av1.y += s1 * t1.y; av1.z += s1 * t1.z; av1.w += s1 * t1.w;
            }
            if (A2) {
                float4 t0 = *(const float4*)(Ap2a + kn), t1 = *(const float4*)(Ap2b + kn);
                av0.x += s2 * t0.x; av0.y += s2 * t0.y; av0.z += s2 * t0.z; av0.w += s2 * t0.w;
                av1.x += s2 * t1.x; av1.y += s2 * t1.y; av1.z += s2 * t1.z; av1.w += s2 * t1.w;
            }
            bv = *(const float4*)(Wp + (size_t)kn * N);
        }

        #pragma unroll
        for (int kk = 0; kk < 16; kk++) {
            float4 aA = *(const float4*)&As[kk][tm];
            float4 aB = *(const float4*)&As[kk][tm + 4];
            ulonglong2 b2 = *(const ulonglong2*)&Bs[kk][tn];
            ull s_[8];
            SPLAT2(s_[0], aA.x); SPLAT2(s_[1], aA.y);
            SPLAT2(s_[2], aA.z); SPLAT2(s_[3], aA.w);
            SPLAT2(s_[4], aB.x); SPLAT2(s_[5], aB.y);
            SPLAT2(s_[6], aB.z); SPLAT2(s_[7], aB.w);
            #pragma unroll
            for (int i = 0; i < 8; i++) {
                FMA2(acc2[i][0], s_[i], b2.x);
                FMA2(acc2[i][1], s_[i], b2.y);
            }
        }
        __syncthreads();
        if (last) break;
    }

    #pragma unroll
    for (int i = 0; i < 8; i++) {
        int m = bm + tm + i;
        size_t crow = permC ? ((size_t)(m & 31) * T_ + (m >> 5)) : (size_t)m;
        float* cp = C + crow * N + bn + tn;
        #pragma unroll
        for (int jp = 0; jp < 2; jp++) {
            float2 v = *reinterpret_cast<float2*>(&acc2[i][jp]);
            cp[2 * jp + 0] = v.x + bias[bn + tn + 2 * jp + 0];
            cp[2 * jp + 1] = v.y + bias[bn + tn + 2 * jp + 1];
        }
    }
}

// ---------------- host orchestration -----------------------------------------
static void launch_scan(const float* R, const float* brec, const float* h0vec,
                        const float* xw, float* out)
{
    cudaLaunchConfig_t cfg = {};
    cfg.gridDim  = dim3(NCTA_SCAN, 1, 1);
    cfg.blockDim = dim3(256, 1, 1);
    cfg.dynamicSmemBytes = SMEM_BYTES;
    cudaLaunchAttribute attrs[1];
    attrs[0].id = cudaLaunchAttributeClusterDimension;
    attrs[0].val.clusterDim.x = CLUSTER;
    attrs[0].val.clusterDim.y = 1;
    attrs[0].val.clusterDim.z = 1;
    cfg.attrs = attrs;
    cfg.numAttrs = 1;
    cudaLaunchKernelEx(&cfg, scan_kernel, R, brec, h0vec, xw, out);
}

extern "C" void kernel_launch(void* const* d_in, const int* in_sizes, int n_in,
                              void* d_out, int out_size)
{
    const float* x   = (const float*)d_in[0];
    const float* k0  = (const float*)d_in[1];
    const float* r0  = (const float*)d_in[2];
    const float* b0  = (const float*)d_in[3];
    const float* ks  = (const float*)d_in[4];
    const float* rs  = (const float*)d_in[5];
    const float* bs  = (const float*)d_in[6];
    const float* h00 = (const float*)d_in[7];
    const float* h01 = (const float*)d_in[8];
    const float* h02 = (const float*)d_in[9];
    const float* a   = (const float*)d_in[10];
    const float* wd  = (const float*)d_in[11];
    const float* bd  = (const float*)d_in[12];

    float *xw, *out0, *p0, *p1;
    cudaGetSymbolAddress((void**)&xw,   g_xw);
    cudaGetSymbolAddress((void**)&out0, g_out0);
    cudaGetSymbolAddress((void**)&p0,   g_pred0);
    cudaGetSymbolAddress((void**)&p1,   g_pred1);

    // idempotent attribute setup (host-side, not stream-ordered)
    cudaFuncSetAttribute(scan_kernel,
                         cudaFuncAttributeMaxDynamicSharedMemorySize, SMEM_BYTES);
    cudaFuncSetAttribute(scan_kernel,
                         cudaFuncAttributeNonPortableClusterSizeAllowed, 1);

    const int M = B_ * T_;
    dim3 gridW(M / 128, G3 / 64);   // 256 x 24
    dim3 gridF(M / 128, D_ / 64);   // 256 x 4

    // ---- layer 0: xw = x @ k0 + b_in ----
    gemm_kernel<<<gridW, 256>>>(x, 0, 0, a, 0, 0, k0, b0, xw, M, G3, D_, 1, 0);
    launch_scan(r0, b0 + G3, h00, xw, out0);

    // ---- layer 1: input = out0 ----
    gemm_kernel<<<gridW, 256>>>(out0, 0, 0, a, 0, 0, ks, bs, xw, M, G3, U_, 0, 0);
    launch_scan(rs, bs + G3, h01, xw, p0);

    // ---- layer 2: input = out0 + a[0]*pred0 ----
    gemm_kernel<<<gridW, 256>>>(out0, p0, 0, a, 0, 0, ks, bs, xw, M, G3, U_, 0, 0);
    launch_scan(rs, bs + G3, h02, xw, p1);

    // ---- final: (out0 + a[1]*pred0 + a[2]*pred1) @ wd + bd -> [B,T,D] ----
    gemm_kernel<<<gridF, 256>>>(out0, p0, p1, a, 1, 2, wd, bd,
                                (float*)d_out, M, D_, U_, 0, 1);
}

// round 14
// speedup vs baseline: 1.5579x; 1.2943x over previous
#include <cuda_runtime.h>
#include <math.h>
#include <stdint.h>

#define B_  32
#define T_  1024
#define D_  256
#define U_  512
#define G3  1536          // 3*U
#define NCTA_SCAN 128
#define NGRP 2            // 2 independent batch groups
#define GCTA 64           // CTAs per group
#define GB   16           // batches per group
#define NSTEP (T_ + 2)    // pipelined fused steps
// dynamic SMEM: 3 weight matrices x 24 cols x 512 k
#define WS_BYTES (3 * 24 * U_ * 4)   // 147456

typedef unsigned long long ull;

// packed fp32x2 FMA: d = a*b + d (elementwise on the two fp32 halves)
#define FMA2(d_, a_, b_) \
    asm("fma.rn.f32x2 %0, %1, %2, %3;" : "=l"(d_) : "l"(a_), "l"(b_), "l"(d_))
// splat a scalar float into both halves of a 64-bit packed reg
#define SPLAT2(d_, s_) \
    asm("mov.b64 %0, {%1, %1};" : "=l"(d_) : "r"(__float_as_uint(s_)))

// fast sigmoid / tanh via MUFU.EX2 + MUFU.RCP (~1-2e-7 rel err)
__device__ __forceinline__ float fsig(float x) {
    float e, r;
    asm("ex2.approx.f32 %0, %1;" : "=f"(e) : "f"(x * -1.442695041f));
    asm("rcp.approx.f32 %0, %1;" : "=f"(r) : "f"(1.0f + e));
    return r;
}
__device__ __forceinline__ float ftanh(float x) {
    float e, r;
    asm("ex2.approx.f32 %0, %1;" : "=f"(e) : "f"(x * -2.885390082f));
    asm("rcp.approx.f32 %0, %1;" : "=f"(r) : "f"(1.0f + e));
    return fmaf(2.0f, r, -1.0f);
}

// ---------------- scratch (device globals: allocation-free contract) ----------
__device__ float g_xw[(size_t)T_ * B_ * G3];     // [T,B,3U] layer-0 gate pre-acts
__device__ float g_out0[(size_t)T_ * B_ * U_];   // layer-0 outputs [T,B,U]
__device__ float g_pred0[(size_t)T_ * B_ * U_];  // layer-1 outputs
__device__ float g_pred1[(size_t)T_ * B_ * U_];  // layer-2 outputs
__device__ float g_h[3][2][B_ * U_];             // per-layer double-buffered h
__device__ unsigned g_bar_count[NGRP * 32];      // per-group, 128B apart
__device__ volatile unsigned g_bar_gen[NGRP * 32];

// ---------------- per-group barrier (R10-proven): atomic arrive + spinner -----
__device__ __forceinline__ void group_barrier(int grp, unsigned target) {
    __syncthreads();
    if (threadIdx.x == 0) {
        __threadfence();                           // release all prior stores
        unsigned arrived = atomicAdd(&g_bar_count[grp * 32], 1u);
        if (arrived == GCTA - 1u) {
            g_bar_count[grp * 32] = 0;
            __threadfence();
            g_bar_gen[grp * 32] = target;          // release group's spinners
        } else {
            while (g_bar_gen[grp * 32] < target) { }
        }
        __threadfence();                           // acquire
    }
    __syncthreads();
}

// ---------------- one mat-vec pass: acc[4][12] over 512 k, compact butterfly --
// wsp: warp's 12 weight cols [c][512] in SMEM. vA (and optional vB, scaled by
// a0p) are input vectors, batch-major with stride U_, base at this warp's b0.
// Act lanes (l<16) receive S[0..2] = reduced (z,r,h) sums for (batch lb, unit uj).
template<bool DUAL>
__device__ __forceinline__ void pass_mv(
    const float* __restrict__ wsp,
    const float* __restrict__ vA,
    const float* __restrict__ vB,
    ull a0p, int l,
    unsigned bit0, unsigned bit1, unsigned bit2, unsigned bit3,
    float* __restrict__ S)
{
    ull acc[4][12];
    #pragma unroll
    for (int b = 0; b < 4; b++)
        #pragma unroll
        for (int c = 0; c < 12; c++) acc[b][c] = 0ull;

    #pragma unroll
    for (int i2 = 0; i2 < 4; i2++) {
        const int ko = 4 * l + 128 * i2;
        ulonglong2 hq[4];
        #pragma unroll
        for (int b = 0; b < 4; b++) {
            hq[b] = __ldcg((const ulonglong2*)(vA + b * U_ + ko));
            if (DUAL) {
                ulonglong2 pq = __ldcg((const ulonglong2*)(vB + b * U_ + ko));
                FMA2(hq[b].x, pq.x, a0p);          // hq = vA + a0*vB
                FMA2(hq[b].y, pq.y, a0p);
            }
        }
        #pragma unroll
        for (int c = 0; c < 12; c++) {
            ulonglong2 wq = *(const ulonglong2*)(wsp + c * U_ + ko);
            #pragma unroll
            for (int b = 0; b < 4; b++) {
                FMA2(acc[b][c], hq[b].x, wq.x);
                FMA2(acc[b][c], hq[b].y, wq.y);
            }
        }
    }

    float A[4][12];
    #pragma unroll
    for (int b = 0; b < 4; b++)
        #pragma unroll
        for (int c = 0; c < 12; c++) {
            float2 v = *reinterpret_cast<float2*>(&acc[b][c]);
            A[b][c] = v.x + v.y;
        }

    // compacted butterfly (verified rounds 4/7-13)
    #pragma unroll
    for (int b = 0; b < 4; b++)
        #pragma unroll
        for (int c = 0; c < 12; c++)
            A[b][c] += __shfl_xor_sync(0xffffffffu, A[b][c], 16);
    float B8[2][12];
    #pragma unroll
    for (int b2 = 0; b2 < 2; b2++)
        #pragma unroll
        for (int c = 0; c < 12; c++) {
            float keep = bit3 ? A[2 + b2][c] : A[b2][c];
            float send = bit3 ? A[b2][c]     : A[2 + b2][c];
            B8[b2][c] = keep + __shfl_xor_sync(0xffffffffu, send, 8);
        }
    float B4[12];
    #pragma unroll
    for (int c = 0; c < 12; c++) {
        float keep = bit2 ? B8[1][c] : B8[0][c];
        float send = bit2 ? B8[0][c] : B8[1][c];
        B4[c] = keep + __shfl_xor_sync(0xffffffffu, send, 4);
    }
    float B2[3][2];
    #pragma unroll
    for (int g = 0; g < 3; g++)
        #pragma unroll
        for (int j = 0; j < 2; j++) {
            float keep = bit1 ? B4[g * 4 + 2 + j] : B4[g * 4 + j];
            float send = bit1 ? B4[g * 4 + j]     : B4[g * 4 + 2 + j];
            B2[g][j] = keep + __shfl_xor_sync(0xffffffffu, send, 2);
        }
    #pragma unroll
    for (int g = 0; g < 3; g++) {
        float keep = bit0 ? B2[g][1] : B2[g][0];
        float send = bit0 ? B2[g][0] : B2[g][1];
        S[g] = keep + __shfl_xor_sync(0xffffffffu, send, 1);
    }
}

// ---------------- fused 3-layer pipelined GRU scan ----------------------------
// 2 groups x 64 CTAs. Group owns 16 batches; CTA owns 8 units (same indices
// for all 3 layers). Fused step s: layer0@t=s, layer1@t=s-1, layer2@t=s-2.
// Skip-layer input projections (out0@ks, (out0+a0*pred0)@ks) computed in-scan.
__global__ void __launch_bounds__(256, 1) scan_kernel(
    const float* __restrict__ r0,     // layer0 recurrent [U,3U]
    const float* __restrict__ ks,     // skip-layer input kernel [U,3U]
    const float* __restrict__ rs,     // skip-layer recurrent [U,3U]
    const float* __restrict__ b0rec,  // layer0 recurrent bias [3U]
    const float* __restrict__ bsin,   // skip input bias [3U]
    const float* __restrict__ bsrec,  // skip recurrent bias [3U]
    const float* __restrict__ h00,
    const float* __restrict__ h01,
    const float* __restrict__ h02,
    const float* __restrict__ avec)
{
    extern __shared__ float ws[];     // [3 matrices][24 cols][512 k]

    const int tid = threadIdx.x;
    const int grp = blockIdx.x >> 6;          // 0..1
    const int cic = blockIdx.x & 63;          // CTA within group
    const int u0  = cic * 8;                  // first unit owned
    const int bbase = grp * GB;               // first batch of group

    // Preload 3 weight matrices' 24-col shares.
    #pragma unroll
    for (int m = 0; m < 3; m++) {
        const float* W = (m == 0) ? r0 : (m == 1) ? ks : rs;
        float* wsm = ws + m * 24 * U_;
        for (int idx = tid; idx < 24 * U_; idx += 256) {
            int uo = idx & 7;
            int g  = (idx >> 3) % 3;
            int k  = idx / 24;
            int c  = (uo >> 2) * 12 + g * 4 + (uo & 3);
            wsm[c * U_ + k] = W[(size_t)k * G3 + g * U_ + u0 + uo];
        }
    }
    // h init (parity-0 buffers): CTA writes its 16b x 8u slice of each layer.
    if (tid < 128) {
        int b = tid >> 3, uo = tid & 7;
        int i = (bbase + b) * U_ + u0 + uo;
        g_h[0][0][i] = h00[u0 + uo];
        g_h[1][0][i] = h01[u0 + uo];
        g_h[2][0][i] = h02[u0 + uo];
    }

    const int w  = tid >> 5, l = tid & 31;
    const int q  = w >> 1;                    // batch quad 0..3
    const int ch = w & 1;                     // col half 0..1
    const int b0 = bbase + q * 4;             // warp's first batch
    const float* ws0 = ws + ch * 6144;                 // r0 share
    const float* wsK = ws + 24 * U_ + ch * 6144;       // ks share
    const float* wsR = ws + 48 * U_ + ch * 6144;       // rs share

    const int lb = l >> 2, uj = l & 3;
    const int gb = b0 + lb;                   // batch (act lanes)
    const int gu = u0 + ch * 4 + uj;          // unit (act lanes)
    const bool act = (l < 16);
    const unsigned bit0 = l & 1, bit1 = (l >> 1) & 1;
    const unsigned bit2 = (l >> 2) & 1, bit3 = (l >> 3) & 1;

    float b0z = 0.f, b0r = 0.f, b0h = 0.f;    // layer0 recurrent bias
    float biz = 0.f, bir = 0.f, bih = 0.f;    // skip input bias
    float brz = 0.f, brr = 0.f, brh = 0.f;    // skip recurrent bias
    if (act) {
        b0z = b0rec[gu];        b0r = b0rec[U_ + gu];   b0h = b0rec[2 * U_ + gu];
        biz = bsin[gu];         bir = bsin[U_ + gu];    bih = bsin[2 * U_ + gu];
        brz = bsrec[gu];        brr = bsrec[U_ + gu];   brh = bsrec[2 * U_ + gu];
    }
    const float a0 = __ldg(avec);
    ull a0p; SPLAT2(a0p, a0);

    // prefetch layer0 xw for t=0 (R10-proven offsets)
    float xz0 = 0.f, xr0 = 0.f, xh0 = 0.f;
    if (act) {
        const float* xwt = g_xw + (size_t)gb * G3;
        xz0 = __ldg(xwt + gu);
        xr0 = __ldg(xwt + U_ + gu);
        xh0 = __ldg(xwt + 2 * U_ + gu);
    }

    group_barrier(grp, 1u);   // weights + h-init visible group-wide

    for (int s = 0; s < NSTEP; s++) {
        const int t0 = s, t1 = s - 1, t2 = s - 2;
        float S[3], Sx[3];

        // ---- layer 0 @ t0 ----
        if (t0 < T_) {
            const float* hR = g_h[0][t0 & 1];
            float*       hW = g_h[0][(t0 + 1) & 1];
            float hold = act ? __ldcg(hR + gb * U_ + gu) : 0.f;
            pass_mv<false>(ws0, hR + b0 * U_, (const float*)0, a0p, l,
                           bit0, bit1, bit2, bit3, S);
            if (act) {
                float z  = fsig(xz0 + S[0] + b0z);
                float r  = fsig(xr0 + S[1] + b0r);
                float hh = ftanh(xh0 + r * (S[2] + b0h));
                float hnew = z * hold + (1.f - z) * hh;
                g_out0[((size_t)t0 * B_ + gb) * U_ + gu] = hnew;
                __stcg(hW + gb * U_ + gu, hnew + 0.1f * (hold - hnew));
            }
            // prefetch next step's layer0 xw
            if (act && t0 + 1 < T_) {
                const float* xwt = g_xw + ((size_t)(t0 + 1) * B_ + gb) * G3;
                xz0 = __ldg(xwt + gu);
                xr0 = __ldg(xwt + U_ + gu);
                xh0 = __ldg(xwt + 2 * U_ + gu);
            }
        }

        // ---- layer 1 @ t1: inproj(out0[t1] @ ks) then recurrent ----
        if (t1 >= 0 && t1 < T_) {
            const float* vin = g_out0 + ((size_t)t1 * B_ + b0) * U_;
            pass_mv<false>(wsK, vin, (const float*)0, a0p, l,
                           bit0, bit1, bit2, bit3, Sx);
            const float* hR = g_h[1][t1 & 1];
            float*       hW = g_h[1][(t1 + 1) & 1];
            float hold = act ? __ldcg(hR + gb * U_ + gu) : 0.f;
            pass_mv<false>(wsR, hR + b0 * U_, (const float*)0, a0p, l,
                           bit0, bit1, bit2, bit3, S);
            if (act) {
                float z  = fsig((Sx[0] + biz) + S[0] + brz);
                float r  = fsig((Sx[1] + bir) + S[1] + brr);
                float hh = ftanh((Sx[2] + bih) + r * (S[2] + brh));
                float hnew = z * hold + (1.f - z) * hh;
                g_pred0[((size_t)t1 * B_ + gb) * U_ + gu] = hnew;
                __stcg(hW + gb * U_ + gu, hnew + 0.1f * (hold - hnew));
            }
        }

        // ---- layer 2 @ t2: inproj((out0+a0*pred0)[t2] @ ks) then recurrent ----
        if (t2 >= 0) {
            const float* vA = g_out0  + ((size_t)t2 * B_ + b0) * U_;
            const float* vB = g_pred0 + ((size_t)t2 * B_ + b0) * U_;
            pass_mv<true>(wsK, vA, vB, a0p, l, bit0, bit1, bit2, bit3, Sx);
            const float* hR = g_h[2][t2 & 1];
            float*       hW = g_h[2][(t2 + 1) & 1];
            float hold = act ? __ldcg(hR + gb * U_ + gu) : 0.f;
            pass_mv<false>(wsR, hR + b0 * U_, (const float*)0, a0p, l,
                           bit0, bit1, bit2, bit3, S);
            if (act) {
                float z  = fsig((Sx[0] + biz) + S[0] + brz);
                float r  = fsig((Sx[1] + bir) + S[1] + brr);
                float hh = ftanh((Sx[2] + bih) + r * (S[2] + brh));
                float hnew = z * hold + (1.f - z) * hh;
                g_pred1[((size_t)t2 * B_ + gb) * U_ + gu] = hnew;
                __stcg(hW + gb * U_ + gu, hnew + 0.1f * (hold - hnew));
            }
        }

        if (s + 1 < NSTEP) group_barrier(grp, (unsigned)(s + 2));
    }
}

// ---------------- fp32 GEMM: 128x64 tile, 8x4 microtile, reg-staged prefetch --
// C = rowmap(A0 + s1*A1 + s2*A2) @ W + bias. Block (0,0) zeroes barrier state.
__global__ void __launch_bounds__(256) gemm_kernel(
    const float* __restrict__ A0, const float* __restrict__ A1,
    const float* __restrict__ A2, const float* __restrict__ avec,
    int ia1, int ia2,
    const float* __restrict__ W, const float* __restrict__ bias,
    float* __restrict__ C, int M, int N, int K, int permA, int permC)
{
    __shared__ float As[16][132];   // [k][m], +4 pad
    __shared__ float Bs[16][64];

    const int tid = threadIdx.x;
    if (blockIdx.x == 0 && blockIdx.y == 0 && tid < NGRP) {
        g_bar_count[tid * 32] = 0;
        g_bar_gen[tid * 32]   = 0;
    }

    const int bm = blockIdx.x * 128;
    const int bn = blockIdx.y * 64;

    const int ra0 = tid >> 2;
    const int ra1 = ra0 + 64;
    const int ka  = (tid & 3) << 2;
    const int rb = tid >> 4, cb = (tid & 15) << 2;

    const float s1 = A1 ? avec[ia1] : 0.f;
    const float s2 = A2 ? avec[ia2] : 0.f;

    const int m0 = bm + ra0, m1 = bm + ra1;
    const size_t arow0 = permA ? ((size_t)(m0 & 31) * T_ + (m0 >> 5)) : (size_t)m0;
    const size_t arow1 = permA ? ((size_t)(m1 & 31) * T_ + (m1 >> 5)) : (size_t)m1;
    const float* Ap0a = A0 + arow0 * K + ka;
    const float* Ap0b = A0 + arow1 * K + ka;
    const float* Ap1a = A1 ? (A1 + arow0 * K + ka) : (const float*)0;
    const float* Ap1b = A1 ? (A1 + arow1 * K + ka) : (const float*)0;
    const float* Ap2a = A2 ? (A2 + arow0 * K + ka) : (const float*)0;
    const float* Ap2b = A2 ? (A2 + arow1 * K + ka) : (const float*)0;
    const float* Wp   = W + (size_t)rb * N + bn + cb;

    const int tm = (tid >> 4) << 3;
    const int tn = (tid & 15) << 2;

    ull acc2[8][2];
    #pragma unroll
    for (int i = 0; i < 8; i++) { acc2[i][0] = 0ull; acc2[i][1] = 0ull; }

    float4 av0 = *(const float4*)(Ap0a);
    float4 av1 = *(const float4*)(Ap0b);
    if (A1) {
        float4 t0 = *(const float4*)(Ap1a), t1 = *(const float4*)(Ap1b);
        av0.x += s1 * t0.x; av0.y += s1 * t0.y; av0.z += s1 * t0.z; av0.w += s1 * t0.w;
        av1.x += s1 * t1.x; av1.y += s1 * t1.y; av1.z += s1 * t1.z; av1.w += s1 * t1.w;
    }
    if (A2) {
        float4 t0 = *(const float4*)(Ap2a), t1 = *(const float4*)(Ap2b);
        av0.x += s2 * t0.x; av0.y += s2 * t0.y; av0.z += s2 * t0.z; av0.w += s2 * t0.w;
        av1.x += s2 * t1.x; av1.y += s2 * t1.y; av1.z += s2 * t1.z; av1.w += s2 * t1.w;
    }
    float4 bv = *(const float4*)(Wp);

    for (int k0 = 0; ; k0 += 16) {
        As[ka + 0][ra0] = av0.x; As[ka + 1][ra0] = av0.y;
        As[ka + 2][ra0] = av0.z; As[ka + 3][ra0] = av0.w;
        As[ka + 0][ra1] = av1.x; As[ka + 1][ra1] = av1.y;
        As[ka + 2][ra1] = av1.z; As[ka + 3][ra1] = av1.w;
        *(float4*)&Bs[rb][cb] = bv;
        __syncthreads();

        const bool last = (k0 + 16 >= K);
        if (!last) {
            const int kn = k0 + 16;
            av0 = *(const float4*)(Ap0a + kn);
            av1 = *(const float4*)(Ap0b + kn);
            if (A1) {
                float4 t0 = *(const float4*)(Ap1a + kn), t1 = *(const float4*)(Ap1b + kn);
                av0.x += s1 * t0.x; av0.y += s1 * t0.y; av0.z += s1 * t0.z; av0.w += s1 * t0.w;
                av1.x += s1 * t1.x; av1.y += s1 * t1.y; av1.z += s1 * t1.z; av1.w += s1 * t1.w;
            }
            if (A2) {
                float4 t0 = *(const float4*)(Ap2a + kn), t1 = *(const float4*)(Ap2b + kn);
                av0.x += s2 * t0.x; av0.y += s2 * t0.y; av0.z += s2 * t0.z; av0.w += s2 * t0.w;
                av1.x += s2 * t1.x; av1.y += s2 * t1.y; av1.z += s2 * t1.z; av1.w += s2 * t1.w;
            }
            bv = *(const float4*)(Wp + (size_t)kn * N);
        }

        #pragma unroll
        for (int kk = 0; kk < 16; kk++) {
            float4 aA = *(const float4*)&As[kk][tm];
            float4 aB = *(const float4*)&As[kk][tm + 4];
            ulonglong2 b2 = *(const ulonglong2*)&Bs[kk][tn];
            ull s_[8];
            SPLAT2(s_[0], aA.x); SPLAT2(s_[1], aA.y);
            SPLAT2(s_[2], aA.z); SPLAT2(s_[3], aA.w);
            SPLAT2(s_[4], aB.x); SPLAT2(s_[5], aB.y);
            SPLAT2(s_[6], aB.z); SPLAT2(s_[7], aB.w);
            #pragma unroll
            for (int i = 0; i < 8; i++) {
                FMA2(acc2[i][0], s_[i], b2.x);
                FMA2(acc2[i][1], s_[i], b2.y);
            }
        }
        __syncthreads();
        if (last) break;
    }

    #pragma unroll
    for (int i = 0; i < 8; i++) {
        int m = bm + tm + i;
        size_t crow = permC ? ((size_t)(m & 31) * T_ + (m >> 5)) : (size_t)m;
        float* cp = C + crow * N + bn + tn;
        #pragma unroll
        for (int jp = 0; jp < 2; jp++) {
            float2 v = *reinterpret_cast<float2*>(&acc2[i][jp]);
            cp[2 * jp + 0] = v.x + bias[bn + tn + 2 * jp + 0];
            cp[2 * jp + 1] = v.y + bias[bn + tn + 2 * jp + 1];
        }
    }
}

// ---------------- host orchestration -----------------------------------------
extern "C" void kernel_launch(void* const* d_in, const int* in_sizes, int n_in,
                              void* d_out, int out_size)
{
    const float* x   = (const float*)d_in[0];
    const float* k0  = (const float*)d_in[1];
    const float* r0  = (const float*)d_in[2];
    const float* b0  = (const float*)d_in[3];
    const float* ks  = (const float*)d_in[4];
    const float* rs  = (const float*)d_in[5];
    const float* bs  = (const float*)d_in[6];
    const float* h00 = (const float*)d_in[7];
    const float* h01 = (const float*)d_in[8];
    const float* h02 = (const float*)d_in[9];
    const float* a   = (const float*)d_in[10];
    const float* wd  = (const float*)d_in[11];
    const float* bd  = (const float*)d_in[12];

    float *xw, *out0, *p0, *p1;
    cudaGetSymbolAddress((void**)&xw,   g_xw);
    cudaGetSymbolAddress((void**)&out0, g_out0);
    cudaGetSymbolAddress((void**)&p0,   g_pred0);
    cudaGetSymbolAddress((void**)&p1,   g_pred1);

    cudaFuncSetAttribute(scan_kernel,
                         cudaFuncAttributeMaxDynamicSharedMemorySize, WS_BYTES);

    const int M = B_ * T_;
    dim3 gridW(M / 128, G3 / 64);   // 256 x 24
    dim3 gridF(M / 128, D_ / 64);   // 256 x 4

    // ---- layer 0 input projection: xw = x @ k0 + b_in (also zeroes barriers) --
    gemm_kernel<<<gridW, 256>>>(x, 0, 0, a, 0, 0, k0, b0, xw, M, G3, D_, 1, 0);

    // ---- fused 3-layer pipelined scan (produces out0, pred0, pred1) ----------
    scan_kernel<<<NCTA_SCAN, 256, WS_BYTES>>>(r0, ks, rs,
                                              b0 + G3, bs, bs + G3,
                                              h00, h01, h02, a);

    // ---- final: (out0 + a[1]*pred0 + a[2]*pred1) @ wd + bd -> [B,T,D] --------
    gemm_kernel<<<gridF, 256>>>(out0, p0, p1, a, 1, 2, wd, bd,
                                (float*)d_out, M, D_, U_, 0, 1);
}